// round 14
// baseline (speedup 1.0000x reference)
#include <cuda_runtime.h>
#include <cuda_fp16.h>
#include <cuda_bf16.h>

#define T_SEQ 2048
#define NBATCH 16
#define DM 1024
#define HH 512

// ---------------- device scratch ----------------
__device__ __half g_Xh[(size_t)T_SEQ * NBATCH * DM];
__device__ __half g_Wt[2][(size_t)2048 * DM];
__device__ float g_XpF[(size_t)T_SEQ * NBATCH * 2048];
__device__ float g_XpB[(size_t)T_SEQ * NBATCH * 2048];
__device__ __half g_h0[2][4][NBATCH * HH];     // quad-buffered h0 ring
__device__ __half g_h1[2][4][NBATCH * HH];     // quad-buffered h1 ring
__device__ __align__(128) unsigned g_flag[2][2][32];   // [dir][role][blk] step flags

// ---------------- helpers ----------------
__device__ __forceinline__ void mma16h(float c[4], uint4 a, unsigned b0, unsigned b1) {
    asm volatile(
        "mma.sync.aligned.m16n8k16.row.col.f32.f16.f16.f32 "
        "{%0,%1,%2,%3},{%4,%5,%6,%7},{%8,%9},{%0,%1,%2,%3};"
        : "+f"(c[0]), "+f"(c[1]), "+f"(c[2]), "+f"(c[3])
        : "r"(a.x), "r"(a.y), "r"(a.z), "r"(a.w), "r"(b0), "r"(b1));
}

__device__ __forceinline__ uint4 ldsm4(unsigned addr) {
    uint4 r;
    asm volatile("ldmatrix.sync.aligned.m8n8.x4.shared.b16 {%0,%1,%2,%3}, [%4];"
                 : "=r"(r.x), "=r"(r.y), "=r"(r.z), "=r"(r.w) : "r"(addr));
    return r;
}

__device__ __forceinline__ void st_rel(unsigned* p, unsigned v) {
    asm volatile("st.release.gpu.global.u32 [%0], %1;" :: "l"(p), "r"(v) : "memory");
}
__device__ __forceinline__ unsigned ld_acq(const unsigned* p) {
    unsigned v;
    asm volatile("ld.acquire.gpu.global.u32 %0, [%1];" : "=r"(v) : "l"(p) : "memory");
    return v;
}

__device__ __forceinline__ void cpasync16(void* s, const void* g) {
    unsigned ss = (unsigned)__cvta_generic_to_shared(s);
    asm volatile("cp.async.ca.shared.global [%0], [%1], 16;" :: "r"(ss), "l"(g));
}
__device__ __forceinline__ void cp_commit() { asm volatile("cp.async.commit_group;"); }
__device__ __forceinline__ void cp_wait2() { asm volatile("cp.async.wait_group 2;"); }

__device__ __forceinline__ float sigm(float x) { return 1.f / (1.f + __expf(-x)); }
__device__ __forceinline__ float tanh_(float x) {
    float xc = fminf(fmaxf(x, -20.f), 20.f);
    float e = __expf(-2.f * xc);
    return (1.f - e) / (1.f + e);
}

// ---------------- embedding gather (fp16 output) ----------------
__global__ void __launch_bounds__(256) embed_kernel(
    const int* __restrict__ ids, const float* __restrict__ tab, __half* __restrict__ Xh) {
    int i = blockIdx.x * 256 + threadIdx.x;
    int q = i & 127, row = i >> 7;
    int b = row & 15, t = row >> 4;
    int id = ids[b * T_SEQ + t];
    const float4* src = reinterpret_cast<const float4*>(tab) + (size_t)id * 256 + q * 2;
    float4 v0 = src[0], v1 = src[1];
    __half2 h0 = __floats2half2_rn(v0.x, v0.y);
    __half2 h1 = __floats2half2_rn(v0.z, v0.w);
    __half2 h2 = __floats2half2_rn(v1.x, v1.y);
    __half2 h3 = __floats2half2_rn(v1.z, v1.w);
    uint4 out;
    out.x = *(unsigned*)&h0; out.y = *(unsigned*)&h1;
    out.z = *(unsigned*)&h2; out.w = *(unsigned*)&h3;
    reinterpret_cast<uint4*>(Xh)[(size_t)row * 128 + q] = out;
}

// ---------------- W0 -> fp16 transposed [n][k] ----------------
__global__ void __launch_bounds__(256) wconv_kernel(
    const float* __restrict__ fW0, const float* __restrict__ bW0) {
    int idx = blockIdx.x * 256 + threadIdx.x;
    int n = idx & 2047;
    int k = (idx >> 11) & 1023;
    int d = idx >> 21;
    const float* src = d ? bW0 : fW0;
    g_Wt[d][(size_t)n * 1024 + k] = __float2half(src[(size_t)k * 2048 + n]);
}

// ---------------- pipelined FP16 GEMM with ldmatrix fragments ----------------
#define HA_STRIDE 40
#define HA_TILE (128 * HA_STRIDE)
#define GEMMH_SMEM_BYTES (6 * HA_TILE * 2)

__global__ void __launch_bounds__(256) gemmh_kernel(
    const __half* __restrict__ Xh, const __half* __restrict__ Wt,
    const float* __restrict__ bias, float* __restrict__ C) {
    extern __shared__ __align__(16) __half hsm[];
    __half* Ah = hsm;
    __half* Bh = hsm + 3 * HA_TILE;
    const int tid = threadIdx.x, lane = tid & 31, warp = tid >> 5;
    const int wm = warp >> 2, wn = warp & 3;
    const int gid = lane >> 2, tig = lane & 3;
    const int r0 = blockIdx.x * 128, n0 = blockIdx.y * 128;
    float acc[4][4][4] = {};

    const unsigned smb = (unsigned)__cvta_generic_to_shared(hsm);
    const unsigned a_off = (unsigned)((wm * 64 + (lane & 15)) * HA_STRIDE + (lane >> 4) * 8);
    const unsigned b_off = (unsigned)(3 * HA_TILE
                         + (wn * 32 + (lane >> 4) * 8 + (lane & 7)) * HA_STRIDE
                         + ((lane >> 3) & 1) * 8);

    const int c0r = tid >> 2, c0q = (tid & 3) * 8;
    const int c1r = (tid + 256) >> 2, c1q = ((tid + 256) & 3) * 8;

#define COPY_H(s, kt)                                                                      \
    do {                                                                                   \
        int k0_ = (kt) << 5;                                                               \
        cpasync16(Ah + (s) * HA_TILE + c0r * HA_STRIDE + c0q,                              \
                  Xh + (size_t)(r0 + c0r) * 1024 + k0_ + c0q);                             \
        cpasync16(Ah + (s) * HA_TILE + c1r * HA_STRIDE + c1q,                              \
                  Xh + (size_t)(r0 + c1r) * 1024 + k0_ + c1q);                             \
        cpasync16(Bh + (s) * HA_TILE + c0r * HA_STRIDE + c0q,                              \
                  Wt + (size_t)(n0 + c0r) * 1024 + k0_ + c0q);                             \
        cpasync16(Bh + (s) * HA_TILE + c1r * HA_STRIDE + c1q,                              \
                  Wt + (size_t)(n0 + c1r) * 1024 + k0_ + c1q);                             \
    } while (0)

    COPY_H(0, 0); cp_commit();
    COPY_H(1, 1); cp_commit();
    COPY_H(2, 2); cp_commit();

    for (int t = 0; t < 32; ++t) {
        int s = t % 3;
        const unsigned Abase = smb + (s * HA_TILE + a_off) * 2;
        const unsigned Bbase = smb + (s * HA_TILE + b_off) * 2;
        cp_wait2();
        __syncthreads();
#pragma unroll
        for (int kk = 0; kk < 32; kk += 16) {
            uint4 a[4];
#pragma unroll
            for (int mt = 0; mt < 4; ++mt)
                a[mt] = ldsm4(Abase + (mt * 16 * HA_STRIDE + kk) * 2);
            uint4 bp0 = ldsm4(Bbase + kk * 2);
            uint4 bp1 = ldsm4(Bbase + (16 * HA_STRIDE + kk) * 2);
            unsigned bb[4][2] = {{bp0.x, bp0.y}, {bp0.z, bp0.w},
                                 {bp1.x, bp1.y}, {bp1.z, bp1.w}};
#pragma unroll
            for (int mt = 0; mt < 4; ++mt)
#pragma unroll
                for (int nt = 0; nt < 4; ++nt)
                    mma16h(acc[mt][nt], a[mt], bb[nt][0], bb[nt][1]);
        }
        __syncthreads();
        if (t + 3 < 32) COPY_H(s, t + 3);
        cp_commit();
    }
#undef COPY_H

#pragma unroll
    for (int mt = 0; mt < 4; ++mt) {
#pragma unroll
        for (int nt = 0; nt < 4; ++nt) {
#pragma unroll
            for (int e = 0; e < 4; ++e) {
                int row = r0 + wm * 64 + mt * 16 + gid + ((e >> 1) * 8);
                int col = n0 + wn * 32 + nt * 8 + 2 * tig + (e & 1);
                float v = acc[mt][nt][e] + bias[col];
                int tt = row >> 4, b = row & 15;
                int gt = col >> 9, u = col & 511;
                size_t addr = (((size_t)tt * 32 + (u >> 4)) * 64 + gt * 16 + (u & 15)) * 16 + b;
                C[addr] = v;
            }
        }
    }
}

// ---------------- zero exchange/barrier state ----------------
__global__ void __launch_bounds__(256) zero_kernel() {
    int i = blockIdx.x * 256 + threadIdx.x;
    if (i < 32768) ((unsigned*)g_h0)[i] = 0u;
    if (i < 32768) ((unsigned*)g_h1)[i] = 0u;
    if (i < 128) ((unsigned*)g_flag)[i] = 0u;
}

// ---------------- fused layer-pipelined persistent scan ----------------
// Flag-vector barrier (grid.sync pattern): per-block release flags in one
// 128B sector per (dir,role); warp0 polls all 32 with one coalesced acquire.
#define FS_WA_BYTES 131072
#define FS_HS_BYTES 33536
#define FS_GB_BYTES 20480
#define FS_SMEM_BYTES (FS_WA_BYTES + FS_HS_BYTES + FS_GB_BYTES)

template <int ROLE>
__device__ __forceinline__ void scan_loop(
    const unsigned* __restrict__ Wa, __half* hs, float* Gb,
    const float* __restrict__ Xp, float* __restrict__ out,
    unsigned* flag_self, unsigned* flag_other, int dir, int blk, int u0,
    float bi, float bg, float bf, float bo) {
    constexpr int NKS = ROLE ? 16 : 8;
    constexpr int KSLICE = NKS * 16;
    constexpr int HSTR = ROLE ? 1048 : 520;

    const int tid = threadIdx.x, lane = tid & 31, warp = tid >> 5;
    const int nt = warp & 1, kt = warp >> 1;
    const int tig = lane & 3, gid = lane >> 2;
    const int ej = tid & 15, eb = tid >> 4;
    const int q = tid & 63;
    const int b0_ = tid >> 6;

    unsigned Breg[NKS][4][2];
    {
        const unsigned* base = Wa + (warp * NKS * 8) * 32 + lane;
#pragma unroll
        for (int ks = 0; ks < NKS; ++ks)
#pragma unroll
            for (int j = 0; j < 4; ++j) {
                Breg[ks][j][0] = base[(ks * 8 + j * 2 + 0) * 32];
                Breg[ks][j][1] = base[(ks * 8 + j * 2 + 1) * 32];
            }
    }

    unsigned hs_base = (unsigned)__cvta_generic_to_shared(hs)
                     + ((lane & 15) * HSTR + (lane >> 4) * 8 + kt * KSLICE) * 2;

    float c_state = 0.f;
    float* Gp = Gb + kt * 1280;

    float pxi = 0.f, pxg = 0.f, pxf = 0.f, pxo = 0.f;
    if (!ROLE) {
        int t0 = dir ? (T_SEQ - 1) : 0;
        const float* xp = Xp + ((size_t)t0 * 32 + blk) * 1024;
        pxi = xp[(0 * 16 + ej) * 16 + eb];
        pxg = xp[(1 * 16 + ej) * 16 + eb];
        pxf = xp[(2 * 16 + ej) * 16 + eb];
        pxo = xp[(3 * 16 + ej) * 16 + eb];
    }

    for (int s = 0; s <= T_SEQ; ++s) {
        const bool active = ROLE ? (s >= 1) : (s < T_SEQ);
        float h = 0.f;
        if (active) {
            float xi = pxi, xg = pxg, xf = pxf, xo = pxo;

            const uint4* h0src = (const uint4*)g_h0[dir][s & 3];
#pragma unroll
            for (int i = 0; i < 4; ++i) {
                int b = b0_ + i * 4;
                *(uint4*)(hs + b * HSTR + q * 8) = h0src[b * 64 + q];
            }
            if (ROLE) {
                const uint4* h1src = (const uint4*)g_h1[dir][s & 3];
#pragma unroll
                for (int i = 0; i < 4; ++i) {
                    int b = b0_ + i * 4;
                    *(uint4*)(hs + b * HSTR + 512 + q * 8) = h1src[b * 64 + q];
                }
            }
            __syncthreads();

            float c[4][4] = {};
#pragma unroll
            for (int ks = 0; ks < NKS; ++ks) {
                uint4 a = ldsm4(hs_base + ks * 32);
#pragma unroll
                for (int j = 0; j < 4; ++j)
                    mma16h(c[j], a, Breg[ks][j][0], Breg[ks][j][1]);
            }

#pragma unroll
            for (int j = 0; j < 4; ++j) {
                int nb = nt * 32 + j * 8 + 2 * tig;
                Gp[nb * 20 + gid] = c[j][0];
                Gp[(nb + 1) * 20 + gid] = c[j][1];
                Gp[nb * 20 + gid + 8] = c[j][2];
                Gp[(nb + 1) * 20 + gid + 8] = c[j][3];
            }
            __syncthreads();

            float gi = xi + bi, gg = xg + bg, gf = xf + bf, go = xo + bo;
#pragma unroll
            for (int ktt = 0; ktt < 4; ++ktt) {
                const float* Gk = Gb + ktt * 1280;
                gi += Gk[(0 * 16 + ej) * 20 + eb];
                gg += Gk[(1 * 16 + ej) * 20 + eb];
                gf += Gk[(2 * 16 + ej) * 20 + eb];
                go += Gk[(3 * 16 + ej) * 20 + eb];
            }
            float fgate = sigm(gf + 1.0f);
            c_state = fgate * c_state + sigm(gi) * tanh_(gg);
            h = sigm(go) * tanh_(c_state);

            if (!ROLE)
                g_h0[dir][(s + 1) & 3][eb * 512 + u0 + ej] = __float2half(h);
            else
                g_h1[dir][(s + 1) & 3][eb * 512 + u0 + ej] = __float2half(h);

            if (!ROLE && s + 1 < T_SEQ) {
                int tn = dir ? (T_SEQ - 2 - s) : (s + 1);
                const float* xp = Xp + ((size_t)tn * 32 + blk) * 1024;
                pxi = xp[(0 * 16 + ej) * 16 + eb];
                pxg = xp[(1 * 16 + ej) * 16 + eb];
                pxf = xp[(2 * 16 + ej) * 16 + eb];
                pxo = xp[(3 * 16 + ej) * 16 + eb];
            }
        }

        // flag-vector barrier (no fences, no atomics)
        __syncthreads();
        if (tid == 0) st_rel(flag_self + blk, (unsigned)(s + 1));
        if (ROLE && active) {
            int t1 = dir ? (T_SEQ - s) : (s - 1);
            out[((size_t)eb * 2048 + t1) * 1024 + dir * 512 + u0 + ej] = h;
        }
        if (warp == 0) {
            const unsigned t_self = (unsigned)(s + 1);
            const unsigned t_oth = ROLE ? (unsigned)(s + 1)
                                        : (s >= 2 ? (unsigned)(s - 1) : 0u);
            for (;;) {
                unsigned v1 = ld_acq(flag_self + lane);
                unsigned v2 = ld_acq(flag_other + lane);
                if (__all_sync(0xffffffffu, (v1 >= t_self) && (v2 >= t_oth))) break;
            }
        }
        __syncthreads();
    }
}

__global__ void __launch_bounds__(256, 1) fused_scan(
    const float* __restrict__ fW0, const float* __restrict__ fW1,
    const float* __restrict__ bW0, const float* __restrict__ bW1,
    const float* __restrict__ fb1, const float* __restrict__ bb1,
    const float* __restrict__ XpF, const float* __restrict__ XpB,
    float* __restrict__ out) {
    extern __shared__ __align__(16) char smraw[];
    unsigned* Wa = (unsigned*)smraw;
    __half* hs = (__half*)(smraw + FS_WA_BYTES);
    float* Gb = (float*)(smraw + FS_WA_BYTES + FS_HS_BYTES);

    const int bid = blockIdx.x;
    const int dir = bid >> 6;
    const int role = (bid >> 5) & 1;
    const int blk = bid & 31;
    const int u0 = blk * 16;

    const int NKS = role ? 16 : 8;
    const int KSLICE = NKS * 16;
    const int kbase = role ? 0 : 1024;
    const float* Wsrc = role ? (dir ? bW1 : fW1) : (dir ? bW0 : fW0);
    const float* Xp = dir ? XpB : XpF;

    const int tid = threadIdx.x;

    const int total = 2048 * NKS;
    const int nks_shift = role ? 4 : 3;
    for (int idx = tid; idx < total; idx += 256) {
        int lane = idx & 31;
        int r = (idx >> 5) & 1;
        int j = (idx >> 6) & 3;
        int rest = idx >> 8;
        int ks = rest & (NKS - 1);
        int w = rest >> nks_shift;
        int ntl = w & 1, ktl = w >> 1;
        int lgid = lane >> 2, ltig = lane & 3;
        int k = kbase + ktl * KSLICE + ks * 16 + 2 * ltig + r * 8;
        int nl = ntl * 32 + j * 8 + lgid;
        int col = ((nl >> 4) << 9) + u0 + (nl & 15);
        __half2 v = __floats2half2_rn(Wsrc[(size_t)k * 2048 + col],
                                      Wsrc[(size_t)(k + 1) * 2048 + col]);
        Wa[idx] = *(unsigned*)&v;
    }
    __syncthreads();

    float bi = 0.f, bg = 0.f, bf = 0.f, bo = 0.f;
    if (role) {
        const float* bias = dir ? bb1 : fb1;
        int ej = tid & 15;
        bi = bias[0 * 512 + u0 + ej];
        bg = bias[1 * 512 + u0 + ej];
        bf = bias[2 * 512 + u0 + ej];
        bo = bias[3 * 512 + u0 + ej];
    }

    unsigned* flag_self = g_flag[dir][role];
    unsigned* flag_other = g_flag[dir][role ^ 1];
    if (role)
        scan_loop<1>(Wa, hs, Gb, Xp, out, flag_self, flag_other, dir, blk, u0, bi, bg, bf, bo);
    else
        scan_loop<0>(Wa, hs, Gb, Xp, out, flag_self, flag_other, dir, blk, u0, bi, bg, bf, bo);
}

// ---------------- launch ----------------
extern "C" void kernel_launch(void* const* d_in, const int* in_sizes, int n_in,
                              void* d_out, int out_size) {
    const int* ids = (const int*)d_in[0];
    const float* tab = (const float*)d_in[1];
    const float* fW0 = (const float*)d_in[2];
    const float* fb0 = (const float*)d_in[3];
    const float* fW1 = (const float*)d_in[4];
    const float* fb1 = (const float*)d_in[5];
    const float* bW0 = (const float*)d_in[6];
    const float* bb0 = (const float*)d_in[7];
    const float* bW1 = (const float*)d_in[8];
    const float* bb1 = (const float*)d_in[9];
    float* out = (float*)d_out;

    cudaFuncSetAttribute(fused_scan, cudaFuncAttributeMaxDynamicSharedMemorySize,
                         FS_SMEM_BYTES);
    cudaFuncSetAttribute(gemmh_kernel, cudaFuncAttributeMaxDynamicSharedMemorySize,
                         GEMMH_SMEM_BYTES);

    __half *Xh, *Wt0, *Wt1;
    float *XpF, *XpB;
    cudaGetSymbolAddress((void**)&Xh, g_Xh);
    cudaGetSymbolAddress((void**)&Wt0, g_Wt);
    Wt1 = Wt0 + (size_t)2048 * 1024;
    cudaGetSymbolAddress((void**)&XpF, g_XpF);
    cudaGetSymbolAddress((void**)&XpB, g_XpB);

    embed_kernel<<<(T_SEQ * NBATCH * 128) / 256, 256>>>(ids, tab, Xh);
    wconv_kernel<<<(2 * 2048 * 1024) / 256, 256>>>(fW0, bW0);

    dim3 gg(256, 16);
    gemmh_kernel<<<gg, 256, GEMMH_SMEM_BYTES>>>(Xh, Wt0, fb0, XpF);
    gemmh_kernel<<<gg, 256, GEMMH_SMEM_BYTES>>>(Xh, Wt1, bb0, XpB);
    zero_kernel<<<128, 256>>>();
    fused_scan<<<128, 256, FS_SMEM_BYTES>>>(fW0, fW1, bW0, bW1, fb1, bb1,
                                            XpF, XpB, out);
}

// round 15
// speedup vs baseline: 1.6863x; 1.6863x over previous
#include <cuda_runtime.h>
#include <cuda_fp16.h>
#include <cuda_bf16.h>

#define T_SEQ 2048
#define NBATCH 16
#define DM 1024
#define HH 512

// ---------------- device scratch ----------------
__device__ __half g_Xh[(size_t)T_SEQ * NBATCH * DM];
__device__ __half g_Wt[2][(size_t)2048 * DM];
__device__ float g_XpF[(size_t)T_SEQ * NBATCH * 2048];
__device__ float g_XpB[(size_t)T_SEQ * NBATCH * 2048];
__device__ __half g_h0[2][4][NBATCH * HH];     // quad-buffered h0 ring
__device__ __half g_h1[2][4][NBATCH * HH];     // quad-buffered h1 ring
__device__ unsigned g_cnt[2];                  // per-direction joint barrier counter

// ---------------- helpers ----------------
__device__ __forceinline__ void mma16h(float c[4], uint4 a, unsigned b0, unsigned b1) {
    asm volatile(
        "mma.sync.aligned.m16n8k16.row.col.f32.f16.f16.f32 "
        "{%0,%1,%2,%3},{%4,%5,%6,%7},{%8,%9},{%0,%1,%2,%3};"
        : "+f"(c[0]), "+f"(c[1]), "+f"(c[2]), "+f"(c[3])
        : "r"(a.x), "r"(a.y), "r"(a.z), "r"(a.w), "r"(b0), "r"(b1));
}

__device__ __forceinline__ uint4 ldsm4(unsigned addr) {
    uint4 r;
    asm volatile("ldmatrix.sync.aligned.m8n8.x4.shared.b16 {%0,%1,%2,%3}, [%4];"
                 : "=r"(r.x), "=r"(r.y), "=r"(r.z), "=r"(r.w) : "r"(addr));
    return r;
}

__device__ __forceinline__ void cpasync16(void* s, const void* g) {
    unsigned ss = (unsigned)__cvta_generic_to_shared(s);
    asm volatile("cp.async.ca.shared.global [%0], [%1], 16;" :: "r"(ss), "l"(g));
}
__device__ __forceinline__ void cp_commit() { asm volatile("cp.async.commit_group;"); }
__device__ __forceinline__ void cp_wait2() { asm volatile("cp.async.wait_group 2;"); }

__device__ __forceinline__ float sigm(float x) { return 1.f / (1.f + __expf(-x)); }
__device__ __forceinline__ float tanh_(float x) {
    float xc = fminf(fmaxf(x, -20.f), 20.f);
    float e = __expf(-2.f * xc);
    return (1.f - e) / (1.f + e);
}

// ---------------- embedding gather (fp16 output) ----------------
__global__ void __launch_bounds__(256) embed_kernel(
    const int* __restrict__ ids, const float* __restrict__ tab, __half* __restrict__ Xh) {
    int i = blockIdx.x * 256 + threadIdx.x;
    int q = i & 127, row = i >> 7;
    int b = row & 15, t = row >> 4;
    int id = ids[b * T_SEQ + t];
    const float4* src = reinterpret_cast<const float4*>(tab) + (size_t)id * 256 + q * 2;
    float4 v0 = src[0], v1 = src[1];
    __half2 h0 = __floats2half2_rn(v0.x, v0.y);
    __half2 h1 = __floats2half2_rn(v0.z, v0.w);
    __half2 h2 = __floats2half2_rn(v1.x, v1.y);
    __half2 h3 = __floats2half2_rn(v1.z, v1.w);
    uint4 out;
    out.x = *(unsigned*)&h0; out.y = *(unsigned*)&h1;
    out.z = *(unsigned*)&h2; out.w = *(unsigned*)&h3;
    reinterpret_cast<uint4*>(Xh)[(size_t)row * 128 + q] = out;
}

// ---------------- W0 -> fp16 transposed [n][k] ----------------
__global__ void __launch_bounds__(256) wconv_kernel(
    const float* __restrict__ fW0, const float* __restrict__ bW0) {
    int idx = blockIdx.x * 256 + threadIdx.x;
    int n = idx & 2047;
    int k = (idx >> 11) & 1023;
    int d = idx >> 21;
    const float* src = d ? bW0 : fW0;
    g_Wt[d][(size_t)n * 1024 + k] = __float2half(src[(size_t)k * 2048 + n]);
}

// ---------------- pipelined FP16 GEMM with ldmatrix fragments ----------------
#define HA_STRIDE 40
#define HA_TILE (128 * HA_STRIDE)
#define GEMMH_SMEM_BYTES (6 * HA_TILE * 2)

__global__ void __launch_bounds__(256) gemmh_kernel(
    const __half* __restrict__ Xh, const __half* __restrict__ Wt,
    const float* __restrict__ bias, float* __restrict__ C) {
    extern __shared__ __align__(16) __half hsm[];
    __half* Ah = hsm;
    __half* Bh = hsm + 3 * HA_TILE;
    const int tid = threadIdx.x, lane = tid & 31, warp = tid >> 5;
    const int wm = warp >> 2, wn = warp & 3;
    const int gid = lane >> 2, tig = lane & 3;
    const int r0 = blockIdx.x * 128, n0 = blockIdx.y * 128;
    float acc[4][4][4] = {};

    const unsigned smb = (unsigned)__cvta_generic_to_shared(hsm);
    const unsigned a_off = (unsigned)((wm * 64 + (lane & 15)) * HA_STRIDE + (lane >> 4) * 8);
    const unsigned b_off = (unsigned)(3 * HA_TILE
                         + (wn * 32 + (lane >> 4) * 8 + (lane & 7)) * HA_STRIDE
                         + ((lane >> 3) & 1) * 8);

    const int c0r = tid >> 2, c0q = (tid & 3) * 8;
    const int c1r = (tid + 256) >> 2, c1q = ((tid + 256) & 3) * 8;

#define COPY_H(s, kt)                                                                      \
    do {                                                                                   \
        int k0_ = (kt) << 5;                                                               \
        cpasync16(Ah + (s) * HA_TILE + c0r * HA_STRIDE + c0q,                              \
                  Xh + (size_t)(r0 + c0r) * 1024 + k0_ + c0q);                             \
        cpasync16(Ah + (s) * HA_TILE + c1r * HA_STRIDE + c1q,                              \
                  Xh + (size_t)(r0 + c1r) * 1024 + k0_ + c1q);                             \
        cpasync16(Bh + (s) * HA_TILE + c0r * HA_STRIDE + c0q,                              \
                  Wt + (size_t)(n0 + c0r) * 1024 + k0_ + c0q);                             \
        cpasync16(Bh + (s) * HA_TILE + c1r * HA_STRIDE + c1q,                              \
                  Wt + (size_t)(n0 + c1r) * 1024 + k0_ + c1q);                             \
    } while (0)

    COPY_H(0, 0); cp_commit();
    COPY_H(1, 1); cp_commit();
    COPY_H(2, 2); cp_commit();

    for (int t = 0; t < 32; ++t) {
        int s = t % 3;
        const unsigned Abase = smb + (s * HA_TILE + a_off) * 2;
        const unsigned Bbase = smb + (s * HA_TILE + b_off) * 2;
        cp_wait2();
        __syncthreads();
#pragma unroll
        for (int kk = 0; kk < 32; kk += 16) {
            uint4 a[4];
#pragma unroll
            for (int mt = 0; mt < 4; ++mt)
                a[mt] = ldsm4(Abase + (mt * 16 * HA_STRIDE + kk) * 2);
            uint4 bp0 = ldsm4(Bbase + kk * 2);
            uint4 bp1 = ldsm4(Bbase + (16 * HA_STRIDE + kk) * 2);
            unsigned bb[4][2] = {{bp0.x, bp0.y}, {bp0.z, bp0.w},
                                 {bp1.x, bp1.y}, {bp1.z, bp1.w}};
#pragma unroll
            for (int mt = 0; mt < 4; ++mt)
#pragma unroll
                for (int nt = 0; nt < 4; ++nt)
                    mma16h(acc[mt][nt], a[mt], bb[nt][0], bb[nt][1]);
        }
        __syncthreads();
        if (t + 3 < 32) COPY_H(s, t + 3);
        cp_commit();
    }
#undef COPY_H

#pragma unroll
    for (int mt = 0; mt < 4; ++mt) {
#pragma unroll
        for (int nt = 0; nt < 4; ++nt) {
#pragma unroll
            for (int e = 0; e < 4; ++e) {
                int row = r0 + wm * 64 + mt * 16 + gid + ((e >> 1) * 8);
                int col = n0 + wn * 32 + nt * 8 + 2 * tig + (e & 1);
                float v = acc[mt][nt][e] + bias[col];
                int tt = row >> 4, b = row & 15;
                int gt = col >> 9, u = col & 511;
                size_t addr = (((size_t)tt * 32 + (u >> 4)) * 64 + gt * 16 + (u & 15)) * 16 + b;
                C[addr] = v;
            }
        }
    }
}

// ---------------- zero exchange/barrier state ----------------
__global__ void __launch_bounds__(256) zero_kernel() {
    int i = blockIdx.x * 256 + threadIdx.x;
    if (i < 32768) ((unsigned*)g_h0)[i] = 0u;
    if (i < 32768) ((unsigned*)g_h1)[i] = 0u;
    if (i < 2) g_cnt[i] = 0u;
}

// ---------------- fused layer-pipelined persistent scan ----------------
// Transposed recurrent GEMM (h via ldmatrix, weights static in registers).
// R12-proven joint barrier: single counter per direction, tid0-only traffic.
#define FS_WA_BYTES 131072
#define FS_HS_BYTES 33536
#define FS_GB_BYTES 20480
#define FS_SMEM_BYTES (FS_WA_BYTES + FS_HS_BYTES + FS_GB_BYTES)

template <int ROLE>
__device__ __forceinline__ void scan_loop(
    const unsigned* __restrict__ Wa, __half* hs, float* Gb,
    const float* __restrict__ Xp, float* __restrict__ out,
    unsigned* bar, int dir, int blk, int u0,
    float bi, float bg, float bf, float bo) {
    constexpr int NKS = ROLE ? 16 : 8;
    constexpr int KSLICE = NKS * 16;
    constexpr int HSTR = ROLE ? 1048 : 520;

    const int tid = threadIdx.x, lane = tid & 31, warp = tid >> 5;
    const int nt = warp & 1, kt = warp >> 1;
    const int tig = lane & 3, gid = lane >> 2;
    const int ej = tid & 15, eb = tid >> 4;
    const int q = tid & 63;
    const int b0_ = tid >> 6;

    unsigned Breg[NKS][4][2];
    {
        const unsigned* base = Wa + (warp * NKS * 8) * 32 + lane;
#pragma unroll
        for (int ks = 0; ks < NKS; ++ks)
#pragma unroll
            for (int j = 0; j < 4; ++j) {
                Breg[ks][j][0] = base[(ks * 8 + j * 2 + 0) * 32];
                Breg[ks][j][1] = base[(ks * 8 + j * 2 + 1) * 32];
            }
    }

    unsigned hs_base = (unsigned)__cvta_generic_to_shared(hs)
                     + ((lane & 15) * HSTR + (lane >> 4) * 8 + kt * KSLICE) * 2;

    float c_state = 0.f;
    float* Gp = Gb + kt * 1280;

    // prefetch Xp for step 0 (role 0)
    float pxi = 0.f, pxg = 0.f, pxf = 0.f, pxo = 0.f;
    if (!ROLE) {
        int t0 = dir ? (T_SEQ - 1) : 0;
        const float* xp = Xp + ((size_t)t0 * 32 + blk) * 1024;
        pxi = xp[(0 * 16 + ej) * 16 + eb];
        pxg = xp[(1 * 16 + ej) * 16 + eb];
        pxf = xp[(2 * 16 + ej) * 16 + eb];
        pxo = xp[(3 * 16 + ej) * 16 + eb];
    }

    for (int s = 0; s <= T_SEQ; ++s) {
        const bool active = ROLE ? (s >= 1) : (s < T_SEQ);
        float h = 0.f;
        if (active) {
            float xi = pxi, xg = pxg, xf = pxf, xo = pxo;

            const uint4* h0src = (const uint4*)g_h0[dir][s & 3];
#pragma unroll
            for (int i = 0; i < 4; ++i) {
                int b = b0_ + i * 4;
                *(uint4*)(hs + b * HSTR + q * 8) = h0src[b * 64 + q];
            }
            if (ROLE) {
                const uint4* h1src = (const uint4*)g_h1[dir][s & 3];
#pragma unroll
                for (int i = 0; i < 4; ++i) {
                    int b = b0_ + i * 4;
                    *(uint4*)(hs + b * HSTR + 512 + q * 8) = h1src[b * 64 + q];
                }
            }
            __syncthreads();

            float c[4][4] = {};
#pragma unroll
            for (int ks = 0; ks < NKS; ++ks) {
                uint4 a = ldsm4(hs_base + ks * 32);
#pragma unroll
                for (int j = 0; j < 4; ++j)
                    mma16h(c[j], a, Breg[ks][j][0], Breg[ks][j][1]);
            }

#pragma unroll
            for (int j = 0; j < 4; ++j) {
                int nb = nt * 32 + j * 8 + 2 * tig;
                Gp[nb * 20 + gid] = c[j][0];
                Gp[(nb + 1) * 20 + gid] = c[j][1];
                Gp[nb * 20 + gid + 8] = c[j][2];
                Gp[(nb + 1) * 20 + gid + 8] = c[j][3];
            }
            __syncthreads();

            float gi = xi + bi, gg = xg + bg, gf = xf + bf, go = xo + bo;
#pragma unroll
            for (int ktt = 0; ktt < 4; ++ktt) {
                const float* Gk = Gb + ktt * 1280;
                gi += Gk[(0 * 16 + ej) * 20 + eb];
                gg += Gk[(1 * 16 + ej) * 20 + eb];
                gf += Gk[(2 * 16 + ej) * 20 + eb];
                go += Gk[(3 * 16 + ej) * 20 + eb];
            }
            float fgate = sigm(gf + 1.0f);
            c_state = fgate * c_state + sigm(gi) * tanh_(gg);
            h = sigm(go) * tanh_(c_state);

            if (!ROLE)
                g_h0[dir][(s + 1) & 3][eb * 512 + u0 + ej] = __float2half(h);
            else
                g_h1[dir][(s + 1) & 3][eb * 512 + u0 + ej] = __float2half(h);

            // prefetch Xp for next step (overlaps the barrier wait)
            if (!ROLE && s + 1 < T_SEQ) {
                int tn = dir ? (T_SEQ - 2 - s) : (s + 1);
                const float* xp = Xp + ((size_t)tn * 32 + blk) * 1024;
                pxi = xp[(0 * 16 + ej) * 16 + eb];
                pxg = xp[(1 * 16 + ej) * 16 + eb];
                pxf = xp[(2 * 16 + ej) * 16 + eb];
                pxo = xp[(3 * 16 + ej) * 16 + eb];
            }
        }

        // R12-proven joint barrier: one counter, tid0-only arrive + spin
        __threadfence();
        __syncthreads();
        if (tid == 0) atomicAdd(bar, 1u);
        if (ROLE && active) {
            int t1 = dir ? (T_SEQ - s) : (s - 1);
            out[((size_t)eb * 2048 + t1) * 1024 + dir * 512 + u0 + ej] = h;
        }
        if (tid == 0) {
            unsigned tgt = 64u * (unsigned)(s + 1);
            volatile unsigned* p = bar;
            while (*p < tgt) {}
        }
        __syncthreads();
        __threadfence();
    }
}

__global__ void __launch_bounds__(256, 1) fused_scan(
    const float* __restrict__ fW0, const float* __restrict__ fW1,
    const float* __restrict__ bW0, const float* __restrict__ bW1,
    const float* __restrict__ fb1, const float* __restrict__ bb1,
    const float* __restrict__ XpF, const float* __restrict__ XpB,
    float* __restrict__ out) {
    extern __shared__ __align__(16) char smraw[];
    unsigned* Wa = (unsigned*)smraw;
    __half* hs = (__half*)(smraw + FS_WA_BYTES);
    float* Gb = (float*)(smraw + FS_WA_BYTES + FS_HS_BYTES);

    const int bid = blockIdx.x;
    const int dir = bid >> 6;
    const int role = (bid >> 5) & 1;
    const int blk = bid & 31;
    const int u0 = blk * 16;

    const int NKS = role ? 16 : 8;
    const int KSLICE = NKS * 16;
    const int kbase = role ? 0 : 1024;
    const float* Wsrc = role ? (dir ? bW1 : fW1) : (dir ? bW0 : fW0);
    const float* Xp = dir ? XpB : XpF;

    const int tid = threadIdx.x;

    const int total = 2048 * NKS;
    const int nks_shift = role ? 4 : 3;
    for (int idx = tid; idx < total; idx += 256) {
        int lane = idx & 31;
        int r = (idx >> 5) & 1;
        int j = (idx >> 6) & 3;
        int rest = idx >> 8;
        int ks = rest & (NKS - 1);
        int w = rest >> nks_shift;
        int ntl = w & 1, ktl = w >> 1;
        int lgid = lane >> 2, ltig = lane & 3;
        int k = kbase + ktl * KSLICE + ks * 16 + 2 * ltig + r * 8;
        int nl = ntl * 32 + j * 8 + lgid;
        int col = ((nl >> 4) << 9) + u0 + (nl & 15);
        __half2 v = __floats2half2_rn(Wsrc[(size_t)k * 2048 + col],
                                      Wsrc[(size_t)(k + 1) * 2048 + col]);
        Wa[idx] = *(unsigned*)&v;
    }
    __syncthreads();

    float bi = 0.f, bg = 0.f, bf = 0.f, bo = 0.f;
    if (role) {
        const float* bias = dir ? bb1 : fb1;
        int ej = tid & 15;
        bi = bias[0 * 512 + u0 + ej];
        bg = bias[1 * 512 + u0 + ej];
        bf = bias[2 * 512 + u0 + ej];
        bo = bias[3 * 512 + u0 + ej];
    }

    unsigned* bar = &g_cnt[dir];
    if (role)
        scan_loop<1>(Wa, hs, Gb, Xp, out, bar, dir, blk, u0, bi, bg, bf, bo);
    else
        scan_loop<0>(Wa, hs, Gb, Xp, out, bar, dir, blk, u0, bi, bg, bf, bo);
}

// ---------------- launch ----------------
extern "C" void kernel_launch(void* const* d_in, const int* in_sizes, int n_in,
                              void* d_out, int out_size) {
    const int* ids = (const int*)d_in[0];
    const float* tab = (const float*)d_in[1];
    const float* fW0 = (const float*)d_in[2];
    const float* fb0 = (const float*)d_in[3];
    const float* fW1 = (const float*)d_in[4];
    const float* fb1 = (const float*)d_in[5];
    const float* bW0 = (const float*)d_in[6];
    const float* bb0 = (const float*)d_in[7];
    const float* bW1 = (const float*)d_in[8];
    const float* bb1 = (const float*)d_in[9];
    float* out = (float*)d_out;

    cudaFuncSetAttribute(fused_scan, cudaFuncAttributeMaxDynamicSharedMemorySize,
                         FS_SMEM_BYTES);
    cudaFuncSetAttribute(gemmh_kernel, cudaFuncAttributeMaxDynamicSharedMemorySize,
                         GEMMH_SMEM_BYTES);

    __half *Xh, *Wt0, *Wt1;
    float *XpF, *XpB;
    cudaGetSymbolAddress((void**)&Xh, g_Xh);
    cudaGetSymbolAddress((void**)&Wt0, g_Wt);
    Wt1 = Wt0 + (size_t)2048 * 1024;
    cudaGetSymbolAddress((void**)&XpF, g_XpF);
    cudaGetSymbolAddress((void**)&XpB, g_XpB);

    embed_kernel<<<(T_SEQ * NBATCH * 128) / 256, 256>>>(ids, tab, Xh);
    wconv_kernel<<<(2 * 2048 * 1024) / 256, 256>>>(fW0, bW0);

    dim3 gg(256, 16);
    gemmh_kernel<<<gg, 256, GEMMH_SMEM_BYTES>>>(Xh, Wt0, fb0, XpF);
    gemmh_kernel<<<gg, 256, GEMMH_SMEM_BYTES>>>(Xh, Wt1, bb0, XpB);
    zero_kernel<<<128, 256>>>();
    fused_scan<<<128, 256, FS_SMEM_BYTES>>>(fW0, fW1, bW0, bW1, fb1, bb1,
                                            XpF, XpB, out);
}

// round 16
// speedup vs baseline: 1.7268x; 1.0240x over previous
#include <cuda_runtime.h>
#include <cuda_fp16.h>
#include <cuda_bf16.h>

#define T_SEQ 2048
#define NBATCH 16
#define DM 1024
#define HH 512

// ---------------- device scratch ----------------
__device__ __half g_Xh[(size_t)T_SEQ * NBATCH * DM];
__device__ __half g_Wt[2][(size_t)2048 * DM];
__device__ float g_XpF[(size_t)T_SEQ * NBATCH * 2048];
__device__ float g_XpB[(size_t)T_SEQ * NBATCH * 2048];
__device__ __half g_h0[2][4][NBATCH * HH];     // quad-buffered h0 ring
__device__ __half g_h1[2][4][NBATCH * HH];     // quad-buffered h1 ring
__device__ unsigned g_cnt[2];                  // per-direction joint barrier counter

// ---------------- helpers ----------------
__device__ __forceinline__ void mma16h(float c[4], uint4 a, unsigned b0, unsigned b1) {
    asm volatile(
        "mma.sync.aligned.m16n8k16.row.col.f32.f16.f16.f32 "
        "{%0,%1,%2,%3},{%4,%5,%6,%7},{%8,%9},{%0,%1,%2,%3};"
        : "+f"(c[0]), "+f"(c[1]), "+f"(c[2]), "+f"(c[3])
        : "r"(a.x), "r"(a.y), "r"(a.z), "r"(a.w), "r"(b0), "r"(b1));
}

__device__ __forceinline__ uint4 ldsm4(unsigned addr) {
    uint4 r;
    asm volatile("ldmatrix.sync.aligned.m8n8.x4.shared.b16 {%0,%1,%2,%3}, [%4];"
                 : "=r"(r.x), "=r"(r.y), "=r"(r.z), "=r"(r.w) : "r"(addr));
    return r;
}

__device__ __forceinline__ void cpasync16(void* s, const void* g) {
    unsigned ss = (unsigned)__cvta_generic_to_shared(s);
    asm volatile("cp.async.ca.shared.global [%0], [%1], 16;" :: "r"(ss), "l"(g));
}
__device__ __forceinline__ void cpasync16cg(void* s, const void* g) {   // L2-direct
    unsigned ss = (unsigned)__cvta_generic_to_shared(s);
    asm volatile("cp.async.cg.shared.global [%0], [%1], 16;" :: "r"(ss), "l"(g));
}
__device__ __forceinline__ void cp_commit() { asm volatile("cp.async.commit_group;"); }
__device__ __forceinline__ void cp_wait2() { asm volatile("cp.async.wait_group 2;"); }
__device__ __forceinline__ void cp_wait0() { asm volatile("cp.async.wait_group 0;"); }

__device__ __forceinline__ void bar_arrive_release(unsigned* p) {
    asm volatile("red.release.gpu.global.add.u32 [%0], %1;" :: "l"(p), "r"(1u) : "memory");
}
__device__ __forceinline__ unsigned ld_acquire(const unsigned* p) {
    unsigned v;
    asm volatile("ld.acquire.gpu.global.u32 %0, [%1];" : "=r"(v) : "l"(p) : "memory");
    return v;
}

__device__ __forceinline__ float sigm(float x) { return 1.f / (1.f + __expf(-x)); }
__device__ __forceinline__ float tanh_(float x) {
    float xc = fminf(fmaxf(x, -20.f), 20.f);
    float e = __expf(-2.f * xc);
    return (1.f - e) / (1.f + e);
}

// ---------------- embedding gather (fp16 output) ----------------
__global__ void __launch_bounds__(256) embed_kernel(
    const int* __restrict__ ids, const float* __restrict__ tab, __half* __restrict__ Xh) {
    int i = blockIdx.x * 256 + threadIdx.x;
    int q = i & 127, row = i >> 7;
    int b = row & 15, t = row >> 4;
    int id = ids[b * T_SEQ + t];
    const float4* src = reinterpret_cast<const float4*>(tab) + (size_t)id * 256 + q * 2;
    float4 v0 = src[0], v1 = src[1];
    __half2 h0 = __floats2half2_rn(v0.x, v0.y);
    __half2 h1 = __floats2half2_rn(v0.z, v0.w);
    __half2 h2 = __floats2half2_rn(v1.x, v1.y);
    __half2 h3 = __floats2half2_rn(v1.z, v1.w);
    uint4 out;
    out.x = *(unsigned*)&h0; out.y = *(unsigned*)&h1;
    out.z = *(unsigned*)&h2; out.w = *(unsigned*)&h3;
    reinterpret_cast<uint4*>(Xh)[(size_t)row * 128 + q] = out;
}

// ---------------- W0 -> fp16 transposed [n][k] ----------------
__global__ void __launch_bounds__(256) wconv_kernel(
    const float* __restrict__ fW0, const float* __restrict__ bW0) {
    int idx = blockIdx.x * 256 + threadIdx.x;
    int n = idx & 2047;
    int k = (idx >> 11) & 1023;
    int d = idx >> 21;
    const float* src = d ? bW0 : fW0;
    g_Wt[d][(size_t)n * 1024 + k] = __float2half(src[(size_t)k * 2048 + n]);
}

// ---------------- pipelined FP16 GEMM with ldmatrix fragments ----------------
#define HA_STRIDE 40
#define HA_TILE (128 * HA_STRIDE)
#define GEMMH_SMEM_BYTES (6 * HA_TILE * 2)

__global__ void __launch_bounds__(256) gemmh_kernel(
    const __half* __restrict__ Xh, const __half* __restrict__ Wt,
    const float* __restrict__ bias, float* __restrict__ C) {
    extern __shared__ __align__(16) __half hsm[];
    __half* Ah = hsm;
    __half* Bh = hsm + 3 * HA_TILE;
    const int tid = threadIdx.x, lane = tid & 31, warp = tid >> 5;
    const int wm = warp >> 2, wn = warp & 3;
    const int gid = lane >> 2, tig = lane & 3;
    const int r0 = blockIdx.x * 128, n0 = blockIdx.y * 128;
    float acc[4][4][4] = {};

    const unsigned smb = (unsigned)__cvta_generic_to_shared(hsm);
    const unsigned a_off = (unsigned)((wm * 64 + (lane & 15)) * HA_STRIDE + (lane >> 4) * 8);
    const unsigned b_off = (unsigned)(3 * HA_TILE
                         + (wn * 32 + (lane >> 4) * 8 + (lane & 7)) * HA_STRIDE
                         + ((lane >> 3) & 1) * 8);

    const int c0r = tid >> 2, c0q = (tid & 3) * 8;
    const int c1r = (tid + 256) >> 2, c1q = ((tid + 256) & 3) * 8;

#define COPY_H(s, kt)                                                                      \
    do {                                                                                   \
        int k0_ = (kt) << 5;                                                               \
        cpasync16(Ah + (s) * HA_TILE + c0r * HA_STRIDE + c0q,                              \
                  Xh + (size_t)(r0 + c0r) * 1024 + k0_ + c0q);                             \
        cpasync16(Ah + (s) * HA_TILE + c1r * HA_STRIDE + c1q,                              \
                  Xh + (size_t)(r0 + c1r) * 1024 + k0_ + c1q);                             \
        cpasync16(Bh + (s) * HA_TILE + c0r * HA_STRIDE + c0q,                              \
                  Wt + (size_t)(n0 + c0r) * 1024 + k0_ + c0q);                             \
        cpasync16(Bh + (s) * HA_TILE + c1r * HA_STRIDE + c1q,                              \
                  Wt + (size_t)(n0 + c1r) * 1024 + k0_ + c1q);                             \
    } while (0)

    COPY_H(0, 0); cp_commit();
    COPY_H(1, 1); cp_commit();
    COPY_H(2, 2); cp_commit();

    for (int t = 0; t < 32; ++t) {
        int s = t % 3;
        const unsigned Abase = smb + (s * HA_TILE + a_off) * 2;
        const unsigned Bbase = smb + (s * HA_TILE + b_off) * 2;
        cp_wait2();
        __syncthreads();
#pragma unroll
        for (int kk = 0; kk < 32; kk += 16) {
            uint4 a[4];
#pragma unroll
            for (int mt = 0; mt < 4; ++mt)
                a[mt] = ldsm4(Abase + (mt * 16 * HA_STRIDE + kk) * 2);
            uint4 bp0 = ldsm4(Bbase + kk * 2);
            uint4 bp1 = ldsm4(Bbase + (16 * HA_STRIDE + kk) * 2);
            unsigned bb[4][2] = {{bp0.x, bp0.y}, {bp0.z, bp0.w},
                                 {bp1.x, bp1.y}, {bp1.z, bp1.w}};
#pragma unroll
            for (int mt = 0; mt < 4; ++mt)
#pragma unroll
                for (int nt = 0; nt < 4; ++nt)
                    mma16h(acc[mt][nt], a[mt], bb[nt][0], bb[nt][1]);
        }
        __syncthreads();
        if (t + 3 < 32) COPY_H(s, t + 3);
        cp_commit();
    }
#undef COPY_H

#pragma unroll
    for (int mt = 0; mt < 4; ++mt) {
#pragma unroll
        for (int nt = 0; nt < 4; ++nt) {
#pragma unroll
            for (int e = 0; e < 4; ++e) {
                int row = r0 + wm * 64 + mt * 16 + gid + ((e >> 1) * 8);
                int col = n0 + wn * 32 + nt * 8 + 2 * tig + (e & 1);
                float v = acc[mt][nt][e] + bias[col];
                int tt = row >> 4, b = row & 15;
                int gt = col >> 9, u = col & 511;
                size_t addr = (((size_t)tt * 32 + (u >> 4)) * 64 + gt * 16 + (u & 15)) * 16 + b;
                C[addr] = v;
            }
        }
    }
}

// ---------------- zero exchange/barrier state ----------------
__global__ void __launch_bounds__(256) zero_kernel() {
    int i = blockIdx.x * 256 + threadIdx.x;
    if (i < 32768) ((unsigned*)g_h0)[i] = 0u;
    if (i < 32768) ((unsigned*)g_h1)[i] = 0u;
    if (i < 2) g_cnt[i] = 0u;
}

// ---------------- fused layer-pipelined persistent scan ----------------
// Transposed recurrent GEMM (h via ldmatrix, weights static in registers).
// Barrier: cg::grid_sync pattern (bar.sync -> tid0 red.release -> tid0
// ld.acquire spin -> bar.sync). No threadfence (no CCTL.IVALL per step);
// h ring staged via cp.async.cg (L2-direct) so stale-L1 is impossible.
#define FS_WA_BYTES 131072
#define FS_HS_BYTES 33536
#define FS_GB_BYTES 20480
#define FS_SMEM_BYTES (FS_WA_BYTES + FS_HS_BYTES + FS_GB_BYTES)

template <int ROLE>
__device__ __forceinline__ void scan_loop(
    const unsigned* __restrict__ Wa, __half* hs, float* Gb,
    const float* __restrict__ Xp, float* __restrict__ out,
    unsigned* bar, int dir, int blk, int u0,
    float bi, float bg, float bf, float bo) {
    constexpr int NKS = ROLE ? 16 : 8;
    constexpr int KSLICE = NKS * 16;
    constexpr int HSTR = ROLE ? 1048 : 520;

    const int tid = threadIdx.x, lane = tid & 31, warp = tid >> 5;
    const int nt = warp & 1, kt = warp >> 1;
    const int tig = lane & 3, gid = lane >> 2;
    const int ej = tid & 15, eb = tid >> 4;
    const int q = tid & 63;
    const int b0_ = tid >> 6;

    unsigned Breg[NKS][4][2];
    {
        const unsigned* base = Wa + (warp * NKS * 8) * 32 + lane;
#pragma unroll
        for (int ks = 0; ks < NKS; ++ks)
#pragma unroll
            for (int j = 0; j < 4; ++j) {
                Breg[ks][j][0] = base[(ks * 8 + j * 2 + 0) * 32];
                Breg[ks][j][1] = base[(ks * 8 + j * 2 + 1) * 32];
            }
    }

    unsigned hs_base = (unsigned)__cvta_generic_to_shared(hs)
                     + ((lane & 15) * HSTR + (lane >> 4) * 8 + kt * KSLICE) * 2;

    float c_state = 0.f;
    float* Gp = Gb + kt * 1280;

    // prefetch Xp for step 0 (role 0)
    float pxi = 0.f, pxg = 0.f, pxf = 0.f, pxo = 0.f;
    if (!ROLE) {
        int t0 = dir ? (T_SEQ - 1) : 0;
        const float* xp = Xp + ((size_t)t0 * 32 + blk) * 1024;
        pxi = xp[(0 * 16 + ej) * 16 + eb];
        pxg = xp[(1 * 16 + ej) * 16 + eb];
        pxf = xp[(2 * 16 + ej) * 16 + eb];
        pxo = xp[(3 * 16 + ej) * 16 + eb];
    }

    for (int s = 0; s <= T_SEQ; ++s) {
        const bool active = ROLE ? (s >= 1) : (s < T_SEQ);
        float h = 0.f;
        if (active) {
            float xi = pxi, xg = pxg, xf = pxf, xo = pxo;

            // stage h ring via L2-direct cp.async (no L1 staleness possible)
            const uint4* h0src = (const uint4*)g_h0[dir][s & 3];
#pragma unroll
            for (int i = 0; i < 4; ++i) {
                int b = b0_ + i * 4;
                cpasync16cg(hs + b * HSTR + q * 8, h0src + b * 64 + q);
            }
            if (ROLE) {
                const uint4* h1src = (const uint4*)g_h1[dir][s & 3];
#pragma unroll
                for (int i = 0; i < 4; ++i) {
                    int b = b0_ + i * 4;
                    cpasync16cg(hs + b * HSTR + 512 + q * 8, h1src + b * 64 + q);
                }
            }
            cp_commit();
            cp_wait0();
            __syncthreads();

            float c[4][4] = {};
#pragma unroll
            for (int ks = 0; ks < NKS; ++ks) {
                uint4 a = ldsm4(hs_base + ks * 32);
#pragma unroll
                for (int j = 0; j < 4; ++j)
                    mma16h(c[j], a, Breg[ks][j][0], Breg[ks][j][1]);
            }

#pragma unroll
            for (int j = 0; j < 4; ++j) {
                int nb = nt * 32 + j * 8 + 2 * tig;
                Gp[nb * 20 + gid] = c[j][0];
                Gp[(nb + 1) * 20 + gid] = c[j][1];
                Gp[nb * 20 + gid + 8] = c[j][2];
                Gp[(nb + 1) * 20 + gid + 8] = c[j][3];
            }
            __syncthreads();

            float gi = xi + bi, gg = xg + bg, gf = xf + bf, go = xo + bo;
#pragma unroll
            for (int ktt = 0; ktt < 4; ++ktt) {
                const float* Gk = Gb + ktt * 1280;
                gi += Gk[(0 * 16 + ej) * 20 + eb];
                gg += Gk[(1 * 16 + ej) * 20 + eb];
                gf += Gk[(2 * 16 + ej) * 20 + eb];
                go += Gk[(3 * 16 + ej) * 20 + eb];
            }
            float fgate = sigm(gf + 1.0f);
            c_state = fgate * c_state + sigm(gi) * tanh_(gg);
            h = sigm(go) * tanh_(c_state);

            if (!ROLE)
                g_h0[dir][(s + 1) & 3][eb * 512 + u0 + ej] = __float2half(h);
            else
                g_h1[dir][(s + 1) & 3][eb * 512 + u0 + ej] = __float2half(h);

            // prefetch Xp for next step (overlaps the barrier wait)
            if (!ROLE && s + 1 < T_SEQ) {
                int tn = dir ? (T_SEQ - 2 - s) : (s + 1);
                const float* xp = Xp + ((size_t)tn * 32 + blk) * 1024;
                pxi = xp[(0 * 16 + ej) * 16 + eb];
                pxg = xp[(1 * 16 + ej) * 16 + eb];
                pxf = xp[(2 * 16 + ej) * 16 + eb];
                pxo = xp[(3 * 16 + ej) * 16 + eb];
            }
        }

        // grid-sync-pattern barrier: one counter, tid0-only traffic, no fences
        __syncthreads();
        if (tid == 0) bar_arrive_release(bar);
        if (ROLE && active) {
            int t1 = dir ? (T_SEQ - s) : (s - 1);
            out[((size_t)eb * 2048 + t1) * 1024 + dir * 512 + u0 + ej] = h;
        }
        if (tid == 0) {
            unsigned tgt = 64u * (unsigned)(s + 1);
            while (ld_acquire(bar) < tgt) {}
        }
        __syncthreads();
    }
}

__global__ void __launch_bounds__(256, 1) fused_scan(
    const float* __restrict__ fW0, const float* __restrict__ fW1,
    const float* __restrict__ bW0, const float* __restrict__ bW1,
    const float* __restrict__ fb1, const float* __restrict__ bb1,
    const float* __restrict__ XpF, const float* __restrict__ XpB,
    float* __restrict__ out) {
    extern __shared__ __align__(16) char smraw[];
    unsigned* Wa = (unsigned*)smraw;
    __half* hs = (__half*)(smraw + FS_WA_BYTES);
    float* Gb = (float*)(smraw + FS_WA_BYTES + FS_HS_BYTES);

    const int bid = blockIdx.x;
    const int dir = bid >> 6;
    const int role = (bid >> 5) & 1;
    const int blk = bid & 31;
    const int u0 = blk * 16;

    const int NKS = role ? 16 : 8;
    const int KSLICE = NKS * 16;
    const int kbase = role ? 0 : 1024;
    const float* Wsrc = role ? (dir ? bW1 : fW1) : (dir ? bW0 : fW0);
    const float* Xp = dir ? XpB : XpF;

    const int tid = threadIdx.x;

    const int total = 2048 * NKS;
    const int nks_shift = role ? 4 : 3;
    for (int idx = tid; idx < total; idx += 256) {
        int lane = idx & 31;
        int r = (idx >> 5) & 1;
        int j = (idx >> 6) & 3;
        int rest = idx >> 8;
        int ks = rest & (NKS - 1);
        int w = rest >> nks_shift;
        int ntl = w & 1, ktl = w >> 1;
        int lgid = lane >> 2, ltig = lane & 3;
        int k = kbase + ktl * KSLICE + ks * 16 + 2 * ltig + r * 8;
        int nl = ntl * 32 + j * 8 + lgid;
        int col = ((nl >> 4) << 9) + u0 + (nl & 15);
        __half2 v = __floats2half2_rn(Wsrc[(size_t)k * 2048 + col],
                                      Wsrc[(size_t)(k + 1) * 2048 + col]);
        Wa[idx] = *(unsigned*)&v;
    }
    __syncthreads();

    float bi = 0.f, bg = 0.f, bf = 0.f, bo = 0.f;
    if (role) {
        const float* bias = dir ? bb1 : fb1;
        int ej = tid & 15;
        bi = bias[0 * 512 + u0 + ej];
        bg = bias[1 * 512 + u0 + ej];
        bf = bias[2 * 512 + u0 + ej];
        bo = bias[3 * 512 + u0 + ej];
    }

    unsigned* bar = &g_cnt[dir];
    if (role)
        scan_loop<1>(Wa, hs, Gb, Xp, out, bar, dir, blk, u0, bi, bg, bf, bo);
    else
        scan_loop<0>(Wa, hs, Gb, Xp, out, bar, dir, blk, u0, bi, bg, bf, bo);
}

// ---------------- launch ----------------
extern "C" void kernel_launch(void* const* d_in, const int* in_sizes, int n_in,
                              void* d_out, int out_size) {
    const int* ids = (const int*)d_in[0];
    const float* tab = (const float*)d_in[1];
    const float* fW0 = (const float*)d_in[2];
    const float* fb0 = (const float*)d_in[3];
    const float* fW1 = (const float*)d_in[4];
    const float* fb1 = (const float*)d_in[5];
    const float* bW0 = (const float*)d_in[6];
    const float* bb0 = (const float*)d_in[7];
    const float* bW1 = (const float*)d_in[8];
    const float* bb1 = (const float*)d_in[9];
    float* out = (float*)d_out;

    cudaFuncSetAttribute(fused_scan, cudaFuncAttributeMaxDynamicSharedMemorySize,
                         FS_SMEM_BYTES);
    cudaFuncSetAttribute(gemmh_kernel, cudaFuncAttributeMaxDynamicSharedMemorySize,
                         GEMMH_SMEM_BYTES);

    __half *Xh, *Wt0, *Wt1;
    float *XpF, *XpB;
    cudaGetSymbolAddress((void**)&Xh, g_Xh);
    cudaGetSymbolAddress((void**)&Wt0, g_Wt);
    Wt1 = Wt0 + (size_t)2048 * 1024;
    cudaGetSymbolAddress((void**)&XpF, g_XpF);
    cudaGetSymbolAddress((void**)&XpB, g_XpB);

    embed_kernel<<<(T_SEQ * NBATCH * 128) / 256, 256>>>(ids, tab, Xh);
    wconv_kernel<<<(2 * 2048 * 1024) / 256, 256>>>(fW0, bW0);

    dim3 gg(256, 16);
    gemmh_kernel<<<gg, 256, GEMMH_SMEM_BYTES>>>(Xh, Wt0, fb0, XpF);
    gemmh_kernel<<<gg, 256, GEMMH_SMEM_BYTES>>>(Xh, Wt1, bb0, XpB);
    zero_kernel<<<128, 256>>>();
    fused_scan<<<128, 256, FS_SMEM_BYTES>>>(fW0, fW1, bW0, bW1, fb1, bb1,
                                            XpF, XpB, out);
}

// round 17
// speedup vs baseline: 1.8096x; 1.0480x over previous
#include <cuda_runtime.h>
#include <cuda_fp16.h>
#include <cuda_bf16.h>

#define T_SEQ 2048
#define NBATCH 16
#define DM 1024
#define HH 512

// ---------------- device scratch ----------------
__device__ __half g_Xh[(size_t)T_SEQ * NBATCH * DM];
__device__ __half g_Wt[2][(size_t)2048 * DM];
__device__ float g_XpF[(size_t)T_SEQ * NBATCH * 2048];
__device__ float g_XpB[(size_t)T_SEQ * NBATCH * 2048];
__device__ __half g_h0[2][4][NBATCH * HH];     // quad-buffered h0 ring
__device__ __half g_h1[2][4][NBATCH * HH];     // quad-buffered h1 ring
__device__ __align__(16) unsigned g_cnt[2][2]; // [dir][role] counters, u64-pollable

// ---------------- helpers ----------------
__device__ __forceinline__ void mma16h(float c[4], uint4 a, unsigned b0, unsigned b1) {
    asm volatile(
        "mma.sync.aligned.m16n8k16.row.col.f32.f16.f16.f32 "
        "{%0,%1,%2,%3},{%4,%5,%6,%7},{%8,%9},{%0,%1,%2,%3};"
        : "+f"(c[0]), "+f"(c[1]), "+f"(c[2]), "+f"(c[3])
        : "r"(a.x), "r"(a.y), "r"(a.z), "r"(a.w), "r"(b0), "r"(b1));
}

__device__ __forceinline__ uint4 ldsm4(unsigned addr) {
    uint4 r;
    asm volatile("ldmatrix.sync.aligned.m8n8.x4.shared.b16 {%0,%1,%2,%3}, [%4];"
                 : "=r"(r.x), "=r"(r.y), "=r"(r.z), "=r"(r.w) : "r"(addr));
    return r;
}

__device__ __forceinline__ void cpasync16(void* s, const void* g) {
    unsigned ss = (unsigned)__cvta_generic_to_shared(s);
    asm volatile("cp.async.ca.shared.global [%0], [%1], 16;" :: "r"(ss), "l"(g));
}
__device__ __forceinline__ void cpasync16cg(void* s, const void* g) {   // L2-direct
    unsigned ss = (unsigned)__cvta_generic_to_shared(s);
    asm volatile("cp.async.cg.shared.global [%0], [%1], 16;" :: "r"(ss), "l"(g));
}
__device__ __forceinline__ void cp_commit() { asm volatile("cp.async.commit_group;"); }
__device__ __forceinline__ void cp_wait2() { asm volatile("cp.async.wait_group 2;"); }
__device__ __forceinline__ void cp_wait0() { asm volatile("cp.async.wait_group 0;"); }

__device__ __forceinline__ void bar_arrive_release(unsigned* p) {
    asm volatile("red.release.gpu.global.add.u32 [%0], %1;" :: "l"(p), "r"(1u) : "memory");
}
__device__ __forceinline__ unsigned long long ld_acquire64(const unsigned* p) {
    unsigned long long v;
    asm volatile("ld.acquire.gpu.global.u64 %0, [%1];" : "=l"(v) : "l"(p) : "memory");
    return v;
}

__device__ __forceinline__ float sigm(float x) { return 1.f / (1.f + __expf(-x)); }
__device__ __forceinline__ float tanh_(float x) {
    float xc = fminf(fmaxf(x, -20.f), 20.f);
    float e = __expf(-2.f * xc);
    return (1.f - e) / (1.f + e);
}

// ---------------- embedding gather (fp16 output) ----------------
__global__ void __launch_bounds__(256) embed_kernel(
    const int* __restrict__ ids, const float* __restrict__ tab, __half* __restrict__ Xh) {
    int i = blockIdx.x * 256 + threadIdx.x;
    int q = i & 127, row = i >> 7;
    int b = row & 15, t = row >> 4;
    int id = ids[b * T_SEQ + t];
    const float4* src = reinterpret_cast<const float4*>(tab) + (size_t)id * 256 + q * 2;
    float4 v0 = src[0], v1 = src[1];
    __half2 h0 = __floats2half2_rn(v0.x, v0.y);
    __half2 h1 = __floats2half2_rn(v0.z, v0.w);
    __half2 h2 = __floats2half2_rn(v1.x, v1.y);
    __half2 h3 = __floats2half2_rn(v1.z, v1.w);
    uint4 out;
    out.x = *(unsigned*)&h0; out.y = *(unsigned*)&h1;
    out.z = *(unsigned*)&h2; out.w = *(unsigned*)&h3;
    reinterpret_cast<uint4*>(Xh)[(size_t)row * 128 + q] = out;
}

// ---------------- W0 -> fp16 transposed [n][k] ----------------
__global__ void __launch_bounds__(256) wconv_kernel(
    const float* __restrict__ fW0, const float* __restrict__ bW0) {
    int idx = blockIdx.x * 256 + threadIdx.x;
    int n = idx & 2047;
    int k = (idx >> 11) & 1023;
    int d = idx >> 21;
    const float* src = d ? bW0 : fW0;
    g_Wt[d][(size_t)n * 1024 + k] = __float2half(src[(size_t)k * 2048 + n]);
}

// ---------------- pipelined FP16 GEMM with ldmatrix fragments ----------------
#define HA_STRIDE 40
#define HA_TILE (128 * HA_STRIDE)
#define GEMMH_SMEM_BYTES (6 * HA_TILE * 2)

__global__ void __launch_bounds__(256) gemmh_kernel(
    const __half* __restrict__ Xh, const __half* __restrict__ Wt,
    const float* __restrict__ bias, float* __restrict__ C) {
    extern __shared__ __align__(16) __half hsm[];
    __half* Ah = hsm;
    __half* Bh = hsm + 3 * HA_TILE;
    const int tid = threadIdx.x, lane = tid & 31, warp = tid >> 5;
    const int wm = warp >> 2, wn = warp & 3;
    const int gid = lane >> 2, tig = lane & 3;
    const int r0 = blockIdx.x * 128, n0 = blockIdx.y * 128;
    float acc[4][4][4] = {};

    const unsigned smb = (unsigned)__cvta_generic_to_shared(hsm);
    const unsigned a_off = (unsigned)((wm * 64 + (lane & 15)) * HA_STRIDE + (lane >> 4) * 8);
    const unsigned b_off = (unsigned)(3 * HA_TILE
                         + (wn * 32 + (lane >> 4) * 8 + (lane & 7)) * HA_STRIDE
                         + ((lane >> 3) & 1) * 8);

    const int c0r = tid >> 2, c0q = (tid & 3) * 8;
    const int c1r = (tid + 256) >> 2, c1q = ((tid + 256) & 3) * 8;

#define COPY_H(s, kt)                                                                      \
    do {                                                                                   \
        int k0_ = (kt) << 5;                                                               \
        cpasync16(Ah + (s) * HA_TILE + c0r * HA_STRIDE + c0q,                              \
                  Xh + (size_t)(r0 + c0r) * 1024 + k0_ + c0q);                             \
        cpasync16(Ah + (s) * HA_TILE + c1r * HA_STRIDE + c1q,                              \
                  Xh + (size_t)(r0 + c1r) * 1024 + k0_ + c1q);                             \
        cpasync16(Bh + (s) * HA_TILE + c0r * HA_STRIDE + c0q,                              \
                  Wt + (size_t)(n0 + c0r) * 1024 + k0_ + c0q);                             \
        cpasync16(Bh + (s) * HA_TILE + c1r * HA_STRIDE + c1q,                              \
                  Wt + (size_t)(n0 + c1r) * 1024 + k0_ + c1q);                             \
    } while (0)

    COPY_H(0, 0); cp_commit();
    COPY_H(1, 1); cp_commit();
    COPY_H(2, 2); cp_commit();

    for (int t = 0; t < 32; ++t) {
        int s = t % 3;
        const unsigned Abase = smb + (s * HA_TILE + a_off) * 2;
        const unsigned Bbase = smb + (s * HA_TILE + b_off) * 2;
        cp_wait2();
        __syncthreads();
#pragma unroll
        for (int kk = 0; kk < 32; kk += 16) {
            uint4 a[4];
#pragma unroll
            for (int mt = 0; mt < 4; ++mt)
                a[mt] = ldsm4(Abase + (mt * 16 * HA_STRIDE + kk) * 2);
            uint4 bp0 = ldsm4(Bbase + kk * 2);
            uint4 bp1 = ldsm4(Bbase + (16 * HA_STRIDE + kk) * 2);
            unsigned bb[4][2] = {{bp0.x, bp0.y}, {bp0.z, bp0.w},
                                 {bp1.x, bp1.y}, {bp1.z, bp1.w}};
#pragma unroll
            for (int mt = 0; mt < 4; ++mt)
#pragma unroll
                for (int nt = 0; nt < 4; ++nt)
                    mma16h(acc[mt][nt], a[mt], bb[nt][0], bb[nt][1]);
        }
        __syncthreads();
        if (t + 3 < 32) COPY_H(s, t + 3);
        cp_commit();
    }
#undef COPY_H

#pragma unroll
    for (int mt = 0; mt < 4; ++mt) {
#pragma unroll
        for (int nt = 0; nt < 4; ++nt) {
#pragma unroll
            for (int e = 0; e < 4; ++e) {
                int row = r0 + wm * 64 + mt * 16 + gid + ((e >> 1) * 8);
                int col = n0 + wn * 32 + nt * 8 + 2 * tig + (e & 1);
                float v = acc[mt][nt][e] + bias[col];
                int tt = row >> 4, b = row & 15;
                int gt = col >> 9, u = col & 511;
                size_t addr = (((size_t)tt * 32 + (u >> 4)) * 64 + gt * 16 + (u & 15)) * 16 + b;
                C[addr] = v;
            }
        }
    }
}

// ---------------- zero exchange/barrier state ----------------
__global__ void __launch_bounds__(256) zero_kernel() {
    int i = blockIdx.x * 256 + threadIdx.x;
    if (i < 32768) ((unsigned*)g_h0)[i] = 0u;
    if (i < 32768) ((unsigned*)g_h1)[i] = 0u;
    if (i < 4) ((unsigned*)g_cnt)[i] = 0u;
}

// ---------------- fused layer-pipelined persistent scan ----------------
// Transposed recurrent GEMM (h via ldmatrix, weights static in registers).
// Split per-role counters in one u64 word; tid0 arrives with red.release on
// its role's counter and polls BOTH with a single ld.acquire.u64:
//   L0: self==32(s+1) && other >= 32(s-1)   (WAR slack 2 via quad ring)
//   L1: self==32(s+1) && other >= 32(s+1)   (RAW on h0)
#define FS_WA_BYTES 131072
#define FS_HS_BYTES 33536
#define FS_GB_BYTES 20480
#define FS_SMEM_BYTES (FS_WA_BYTES + FS_HS_BYTES + FS_GB_BYTES)

template <int ROLE>
__device__ __forceinline__ void scan_loop(
    const unsigned* __restrict__ Wa, __half* hs, float* Gb,
    const float* __restrict__ Xp, float* __restrict__ out,
    unsigned* cnt2, int dir, int blk, int u0,
    float bi, float bg, float bf, float bo) {
    constexpr int NKS = ROLE ? 16 : 8;
    constexpr int KSLICE = NKS * 16;
    constexpr int HSTR = ROLE ? 1048 : 520;

    const int tid = threadIdx.x, lane = tid & 31, warp = tid >> 5;
    const int nt = warp & 1, kt = warp >> 1;
    const int tig = lane & 3, gid = lane >> 2;
    const int ej = tid & 15, eb = tid >> 4;
    const int q = tid & 63;
    const int b0_ = tid >> 6;

    unsigned Breg[NKS][4][2];
    {
        const unsigned* base = Wa + (warp * NKS * 8) * 32 + lane;
#pragma unroll
        for (int ks = 0; ks < NKS; ++ks)
#pragma unroll
            for (int j = 0; j < 4; ++j) {
                Breg[ks][j][0] = base[(ks * 8 + j * 2 + 0) * 32];
                Breg[ks][j][1] = base[(ks * 8 + j * 2 + 1) * 32];
            }
    }

    unsigned hs_base = (unsigned)__cvta_generic_to_shared(hs)
                     + ((lane & 15) * HSTR + (lane >> 4) * 8 + kt * KSLICE) * 2;

    float c_state = 0.f;
    float* Gp = Gb + kt * 1280;

    // prefetch Xp for step 0 (role 0)
    float pxi = 0.f, pxg = 0.f, pxf = 0.f, pxo = 0.f;
    if (!ROLE) {
        int t0 = dir ? (T_SEQ - 1) : 0;
        const float* xp = Xp + ((size_t)t0 * 32 + blk) * 1024;
        pxi = xp[(0 * 16 + ej) * 16 + eb];
        pxg = xp[(1 * 16 + ej) * 16 + eb];
        pxf = xp[(2 * 16 + ej) * 16 + eb];
        pxo = xp[(3 * 16 + ej) * 16 + eb];
    }

    for (int s = 0; s <= T_SEQ; ++s) {
        const bool active = ROLE ? (s >= 1) : (s < T_SEQ);
        float h = 0.f;
        if (active) {
            float xi = pxi, xg = pxg, xf = pxf, xo = pxo;

            // stage h ring via L2-direct cp.async (no L1 staleness possible)
            const uint4* h0src = (const uint4*)g_h0[dir][s & 3];
#pragma unroll
            for (int i = 0; i < 4; ++i) {
                int b = b0_ + i * 4;
                cpasync16cg(hs + b * HSTR + q * 8, h0src + b * 64 + q);
            }
            if (ROLE) {
                const uint4* h1src = (const uint4*)g_h1[dir][s & 3];
#pragma unroll
                for (int i = 0; i < 4; ++i) {
                    int b = b0_ + i * 4;
                    cpasync16cg(hs + b * HSTR + 512 + q * 8, h1src + b * 64 + q);
                }
            }
            cp_commit();
            cp_wait0();
            __syncthreads();

            float c[4][4] = {};
#pragma unroll
            for (int ks = 0; ks < NKS; ++ks) {
                uint4 a = ldsm4(hs_base + ks * 32);
#pragma unroll
                for (int j = 0; j < 4; ++j)
                    mma16h(c[j], a, Breg[ks][j][0], Breg[ks][j][1]);
            }

#pragma unroll
            for (int j = 0; j < 4; ++j) {
                int nb = nt * 32 + j * 8 + 2 * tig;
                Gp[nb * 20 + gid] = c[j][0];
                Gp[(nb + 1) * 20 + gid] = c[j][1];
                Gp[nb * 20 + gid + 8] = c[j][2];
                Gp[(nb + 1) * 20 + gid + 8] = c[j][3];
            }
            __syncthreads();

            float gi = xi + bi, gg = xg + bg, gf = xf + bf, go = xo + bo;
#pragma unroll
            for (int ktt = 0; ktt < 4; ++ktt) {
                const float* Gk = Gb + ktt * 1280;
                gi += Gk[(0 * 16 + ej) * 20 + eb];
                gg += Gk[(1 * 16 + ej) * 20 + eb];
                gf += Gk[(2 * 16 + ej) * 20 + eb];
                go += Gk[(3 * 16 + ej) * 20 + eb];
            }
            float fgate = sigm(gf + 1.0f);
            c_state = fgate * c_state + sigm(gi) * tanh_(gg);
            h = sigm(go) * tanh_(c_state);

            if (!ROLE)
                g_h0[dir][(s + 1) & 3][eb * 512 + u0 + ej] = __float2half(h);
            else
                g_h1[dir][(s + 1) & 3][eb * 512 + u0 + ej] = __float2half(h);

            // prefetch Xp for next step (overlaps the barrier wait)
            if (!ROLE && s + 1 < T_SEQ) {
                int tn = dir ? (T_SEQ - 2 - s) : (s + 1);
                const float* xp = Xp + ((size_t)tn * 32 + blk) * 1024;
                pxi = xp[(0 * 16 + ej) * 16 + eb];
                pxg = xp[(1 * 16 + ej) * 16 + eb];
                pxf = xp[(2 * 16 + ej) * 16 + eb];
                pxo = xp[(3 * 16 + ej) * 16 + eb];
            }
        }

        // split barrier: arrive on own counter; one u64 acquire polls both
        __syncthreads();
        if (tid == 0) bar_arrive_release(cnt2 + ROLE);
        if (ROLE && active) {
            int t1 = dir ? (T_SEQ - s) : (s - 1);
            out[((size_t)eb * 2048 + t1) * 1024 + dir * 512 + u0 + ej] = h;
        }
        if (tid == 0) {
            const unsigned t_self = 32u * (unsigned)(s + 1);
            const unsigned t_oth = ROLE ? 32u * (unsigned)(s + 1)
                                        : (s >= 2 ? 32u * (unsigned)(s - 1) : 0u);
            for (;;) {
                unsigned long long v = ld_acquire64(cnt2);
                unsigned c0 = (unsigned)v, c1 = (unsigned)(v >> 32);
                unsigned cs = ROLE ? c1 : c0;
                unsigned co = ROLE ? c0 : c1;
                if (cs >= t_self && co >= t_oth) break;
            }
        }
        __syncthreads();
    }
}

__global__ void __launch_bounds__(256, 1) fused_scan(
    const float* __restrict__ fW0, const float* __restrict__ fW1,
    const float* __restrict__ bW0, const float* __restrict__ bW1,
    const float* __restrict__ fb1, const float* __restrict__ bb1,
    const float* __restrict__ XpF, const float* __restrict__ XpB,
    float* __restrict__ out) {
    extern __shared__ __align__(16) char smraw[];
    unsigned* Wa = (unsigned*)smraw;
    __half* hs = (__half*)(smraw + FS_WA_BYTES);
    float* Gb = (float*)(smraw + FS_WA_BYTES + FS_HS_BYTES);

    const int bid = blockIdx.x;
    const int dir = bid >> 6;
    const int role = (bid >> 5) & 1;
    const int blk = bid & 31;
    const int u0 = blk * 16;

    const int NKS = role ? 16 : 8;
    const int KSLICE = NKS * 16;
    const int kbase = role ? 0 : 1024;
    const float* Wsrc = role ? (dir ? bW1 : fW1) : (dir ? bW0 : fW0);
    const float* Xp = dir ? XpB : XpF;

    const int tid = threadIdx.x;

    const int total = 2048 * NKS;
    const int nks_shift = role ? 4 : 3;
    for (int idx = tid; idx < total; idx += 256) {
        int lane = idx & 31;
        int r = (idx >> 5) & 1;
        int j = (idx >> 6) & 3;
        int rest = idx >> 8;
        int ks = rest & (NKS - 1);
        int w = rest >> nks_shift;
        int ntl = w & 1, ktl = w >> 1;
        int lgid = lane >> 2, ltig = lane & 3;
        int k = kbase + ktl * KSLICE + ks * 16 + 2 * ltig + r * 8;
        int nl = ntl * 32 + j * 8 + lgid;
        int col = ((nl >> 4) << 9) + u0 + (nl & 15);
        __half2 v = __floats2half2_rn(Wsrc[(size_t)k * 2048 + col],
                                      Wsrc[(size_t)(k + 1) * 2048 + col]);
        Wa[idx] = *(unsigned*)&v;
    }
    __syncthreads();

    float bi = 0.f, bg = 0.f, bf = 0.f, bo = 0.f;
    if (role) {
        const float* bias = dir ? bb1 : fb1;
        int ej = tid & 15;
        bi = bias[0 * 512 + u0 + ej];
        bg = bias[1 * 512 + u0 + ej];
        bf = bias[2 * 512 + u0 + ej];
        bo = bias[3 * 512 + u0 + ej];
    }

    unsigned* cnt2 = &g_cnt[dir][0];
    if (role)
        scan_loop<1>(Wa, hs, Gb, Xp, out, cnt2, dir, blk, u0, bi, bg, bf, bo);
    else
        scan_loop<0>(Wa, hs, Gb, Xp, out, cnt2, dir, blk, u0, bi, bg, bf, bo);
}

// ---------------- launch ----------------
extern "C" void kernel_launch(void* const* d_in, const int* in_sizes, int n_in,
                              void* d_out, int out_size) {
    const int* ids = (const int*)d_in[0];
    const float* tab = (const float*)d_in[1];
    const float* fW0 = (const float*)d_in[2];
    const float* fb0 = (const float*)d_in[3];
    const float* fW1 = (const float*)d_in[4];
    const float* fb1 = (const float*)d_in[5];
    const float* bW0 = (const float*)d_in[6];
    const float* bb0 = (const float*)d_in[7];
    const float* bW1 = (const float*)d_in[8];
    const float* bb1 = (const float*)d_in[9];
    float* out = (float*)d_out;

    cudaFuncSetAttribute(fused_scan, cudaFuncAttributeMaxDynamicSharedMemorySize,
                         FS_SMEM_BYTES);
    cudaFuncSetAttribute(gemmh_kernel, cudaFuncAttributeMaxDynamicSharedMemorySize,
                         GEMMH_SMEM_BYTES);

    __half *Xh, *Wt0, *Wt1;
    float *XpF, *XpB;
    cudaGetSymbolAddress((void**)&Xh, g_Xh);
    cudaGetSymbolAddress((void**)&Wt0, g_Wt);
    Wt1 = Wt0 + (size_t)2048 * 1024;
    cudaGetSymbolAddress((void**)&XpF, g_XpF);
    cudaGetSymbolAddress((void**)&XpB, g_XpB);

    embed_kernel<<<(T_SEQ * NBATCH * 128) / 256, 256>>>(ids, tab, Xh);
    wconv_kernel<<<(2 * 2048 * 1024) / 256, 256>>>(fW0, bW0);

    dim3 gg(256, 16);
    gemmh_kernel<<<gg, 256, GEMMH_SMEM_BYTES>>>(Xh, Wt0, fb0, XpF);
    gemmh_kernel<<<gg, 256, GEMMH_SMEM_BYTES>>>(Xh, Wt1, bb0, XpB);
    zero_kernel<<<128, 256>>>();
    fused_scan<<<128, 256, FS_SMEM_BYTES>>>(fW0, fW1, bW0, bW1, fb1, bb1,
                                            XpF, XpB, out);
}